// round 11
// baseline (speedup 1.0000x reference)
#include <cuda_runtime.h>
#include <math.h>
#include <stdint.h>

#define BMAX 8192
typedef unsigned long long u64;

// ---------- packed f32x2 helpers ----------
__device__ __forceinline__ u64 splat2(float w) {
    u64 r; asm("mov.b64 %0,{%1,%1};" : "=l"(r) : "f"(w)); return r;
}
__device__ __forceinline__ void fma2(u64& d, u64 a, u64 b) {
    asm("fma.rn.f32x2 %0,%1,%2,%0;" : "+l"(d) : "l"(a), "l"(b));
}
__device__ __forceinline__ float2 unpack2(u64 v) {
    float2 f; asm("mov.b64 {%0,%1},%2;" : "=f"(f.x), "=f"(f.y) : "l"(v)); return f;
}

// ---------- static scratch ----------
__device__ float g_P1[(size_t)BMAX * 64 * 100];   // pool1 [B][64][10][10]
__device__ float g_P2[(size_t)BMAX * 128 * 25];   // pool2 [B][128][5][5]
__device__ float g_C3[(size_t)BMAX * 256 * 25];   // conv3 [B][256][5][5]
__device__ float g_FT[(size_t)25 * BMAX * 256];   // feats [25][B][256]
__device__ float g_H [(size_t)25 * BMAX * 600];   // hidden [25][B][600]
__device__ float g_PRED[(size_t)25 * BMAX * 10];  // stage1 preds
__device__ float g_SEC [(size_t)25 * BMAX * 10];  // stage2 preds
__device__ float g_NB[(size_t)25 * BMAX * 80];    // neighbor concat
__device__ float g_Wt1[27 * 64],       g_bf1[64];
__device__ float g_Wt2[64 * 9 * 128],  g_bf2[128];
__device__ float g_Wt3[128 * 9 * 256], g_bf3[256];
__device__ float g_Wt4[256 * 9 * 256], g_bf4[256];
__device__ int   g_NEI[25 * 8];

// ---------- single setup kernel: neighbor table + all 4 BN-folds ----------
__global__ void setup_kernel(
    const float* __restrict__ W1, const float* __restrict__ b1, const float* __restrict__ gg1,
    const float* __restrict__ be1, const float* __restrict__ m1, const float* __restrict__ v1,
    const float* __restrict__ W2, const float* __restrict__ b2, const float* __restrict__ gg2,
    const float* __restrict__ be2, const float* __restrict__ m2, const float* __restrict__ v2,
    const float* __restrict__ W3, const float* __restrict__ b3, const float* __restrict__ gg3,
    const float* __restrict__ be3, const float* __restrict__ m3, const float* __restrict__ v3,
    const float* __restrict__ W4, const float* __restrict__ b4, const float* __restrict__ gg4,
    const float* __restrict__ be4, const float* __restrict__ m4, const float* __restrict__ v4) {
    size_t idx = (size_t)blockIdx.x * blockDim.x + threadIdx.x;
    if (idx < 25) {  // neighbor table (exact reference ordering)
        int i = (int)idx;
        const int w = 5, size = 25;
        int nb[8]; int c = 0;
        if (i - w >= 0)                           nb[c++] = i - w;
        if (i % w != 0)                           nb[c++] = i - 1;
        if ((i + 1) % w != 0)                     nb[c++] = i + 1;
        if (i + w < size)                         nb[c++] = i + w;
        if (i - w - 1 >= 0 && i % w != 0)         nb[c++] = i - w - 1;
        if (i - w + 1 >= 0 && (i + 1) % w != 0)   nb[c++] = i - w + 1;
        if (i + w - 1 < size && i % w != 0)       nb[c++] = i + w - 1;
        if (i + w + 1 < size && (i + 1) % w != 0) nb[c++] = i + w + 1;
        while (c < 8) nb[c++] = -1;
        for (int s = 0; s < 8; s++) g_NEI[i * 8 + s] = nb[s];
    }
    const float* Ws[4]  = {W1, W2, W3, W4};
    const float* bs[4]  = {b1, b2, b3, b4};
    const float* gs[4]  = {gg1, gg2, gg3, gg4};
    const float* bes[4] = {be1, be2, be3, be4};
    const float* ms[4]  = {m1, m2, m3, m4};
    const float* vs[4]  = {v1, v2, v3, v4};
    float* Wts[4] = {g_Wt1, g_Wt2, g_Wt3, g_Wt4};
    float* bfs[4] = {g_bf1, g_bf2, g_bf3, g_bf4};
    const int ci[4] = {3, 64, 128, 256}, co[4] = {64, 128, 256, 256};
    size_t off = 0;
    for (int l = 0; l < 4; l++) {
        size_t tot = (size_t)co[l] * ci[l] * 9;
        if (idx >= off && idx < off + tot) {
            int k = (int)(idx - off);
            int oc = k / (ci[l] * 9);
            int r  = k % (ci[l] * 9);
            float sc = gs[l][oc] / sqrtf(vs[l][oc] + 1e-5f);
            Wts[l][(size_t)r * co[l] + oc] = Ws[l][k] * sc;
            if (r == 0) bfs[l][oc] = (bs[l][oc] - ms[l][oc]) * sc + bes[l][oc];
        }
        off += tot;
    }
}

// ---------- conv1(3->64,20x20,p1)+BN+ReLU + pool3s2p1 (scalar; small) ----------
__global__ void __launch_bounds__(128) conv1_pool_kernel(const float* __restrict__ x, int B) {
    __shared__ float xin[3 * 22 * 22];
    __shared__ float ws[27 * 64];
    __shared__ float bsm[64];
    __shared__ float conv[8 * 400];
    int b = blockIdx.x, tid = threadIdx.x;
    for (int i = tid; i < 3 * 22 * 22; i += 128) xin[i] = 0.f;
    for (int i = tid; i < 27 * 64; i += 128) ws[i] = g_Wt1[i];
    if (tid < 64) bsm[tid] = g_bf1[tid];
    __syncthreads();
    const float* xb = x + (size_t)b * 1200;
    for (int i = tid; i < 1200; i += 128) {
        int c = i / 400, p = i % 400;
        xin[c * 484 + (p / 20 + 1) * 22 + (p % 20 + 1)] = xb[i];
    }
    __syncthreads();
    for (int ocb = 0; ocb < 64; ocb += 8) {
        for (int px = tid; px < 400; px += 128) {
            int y = px / 20, xx = px % 20;
            float in[27];
#pragma unroll
            for (int c = 0; c < 3; c++)
#pragma unroll
            for (int ky = 0; ky < 3; ky++)
#pragma unroll
            for (int kx = 0; kx < 3; kx++)
                in[c * 9 + ky * 3 + kx] = xin[c * 484 + (y + ky) * 22 + xx + kx];
#pragma unroll
            for (int o = 0; o < 8; o++) {
                float a = bsm[ocb + o];
#pragma unroll
                for (int j = 0; j < 27; j++) a += in[j] * ws[j * 64 + ocb + o];
                conv[o * 400 + px] = fmaxf(a, 0.f);
            }
        }
        __syncthreads();
        for (int i = tid; i < 800; i += 128) {
            int o = i / 100, p = i % 100, py = p / 10, pxx = p % 10;
            float mx = -1e30f;
            for (int dy = 0; dy < 3; dy++) {
                int yy = 2 * py - 1 + dy; if ((unsigned)yy >= 20u) continue;
                for (int dx = 0; dx < 3; dx++) {
                    int xx2 = 2 * pxx - 1 + dx; if ((unsigned)xx2 >= 20u) continue;
                    mx = fmaxf(mx, conv[o * 400 + yy * 20 + xx2]);
                }
            }
            g_P1[((size_t)b * 64 + ocb + o) * 100 + p] = mx;
        }
        __syncthreads();
    }
}

// ---------- conv2+pool, TWO images per block, packed f32x2, weight prefetch ----------
__global__ void __launch_bounds__(160) conv2_pool_kernel(int B) {
    __shared__ u64 pin[32 * 144];     // [ic][12][12] packed (img0,img1); reused for staging
    int b0 = blockIdx.y * 2, ocg = blockIdx.x, tid = threadIdx.x;
    int oc_l = tid & 31, rp = tid >> 5;
    int oc = ocg * 32 + oc_l;
    for (int i = tid; i < 32 * 144; i += 160) pin[i] = 0ull;
    u64 acc[2][10];
#pragma unroll
    for (int y = 0; y < 2; y++)
#pragma unroll
    for (int xx = 0; xx < 10; xx++) acc[y][xx] = 0ull;
    for (int ch = 0; ch < 2; ch++) {
        __syncthreads();
        for (int i = tid; i < 6400; i += 160) {
            int ic = i / 200, r = i % 200, img = r / 100, p = r % 100;
            ((float*)pin)[((ic * 12 + p / 10 + 1) * 12 + p % 10 + 1) * 2 + img] =
                g_P1[((size_t)(b0 + img) * 64 + ch * 32 + ic) * 100 + p];
        }
        __syncthreads();
        float wf[9];
#pragma unroll
        for (int j = 0; j < 9; j++) wf[j] = g_Wt2[((ch * 32) * 9 + j) * 128 + oc];
        for (int icl = 0; icl < 32; icl++) {
            u64 w2[9];
#pragma unroll
            for (int j = 0; j < 9; j++) w2[j] = splat2(wf[j]);
            if (icl < 31) {
                int icn = ch * 32 + icl + 1;
#pragma unroll
                for (int j = 0; j < 9; j++) wf[j] = g_Wt2[(icn * 9 + j) * 128 + oc];
            }
            const u64* base = &pin[icl * 144];
#pragma unroll
            for (int rr = 0; rr < 4; rr++) {
                int row = rp * 2 + rr;
                u64 r2[12];
                const ulonglong2* rl = (const ulonglong2*)&base[row * 12];
#pragma unroll
                for (int q = 0; q < 6; q++) { ulonglong2 t = rl[q]; r2[2*q] = t.x; r2[2*q+1] = t.y; }
#pragma unroll
                for (int y = 0; y < 2; y++) {
                    int ky = rr - y;
                    if (ky >= 0 && ky < 3) {
#pragma unroll
                        for (int kx = 0; kx < 3; kx++)
#pragma unroll
                        for (int xx = 0; xx < 10; xx++)
                            fma2(acc[y][xx], w2[ky * 3 + kx], r2[xx + kx]);
                    }
                }
            }
        }
    }
    float bias = g_bf2[oc];
    __syncthreads();
#pragma unroll
    for (int y = 0; y < 2; y++)
#pragma unroll
    for (int xx = 0; xx < 10; xx++) {
        float2 f = unpack2(acc[y][xx]);
        int px = (rp * 2 + y) * 10 + xx;
        ((float*)pin)[(oc_l * 100 + px) * 2 + 0] = fmaxf(f.x + bias, 0.f);
        ((float*)pin)[(oc_l * 100 + px) * 2 + 1] = fmaxf(f.y + bias, 0.f);
    }
    __syncthreads();
    for (int i = tid; i < 1600; i += 160) {
        int o = i / 50, r = i % 50, img = r / 25, p = r % 25;
        int py = p / 5, pxx = p % 5;
        float mx = -1e30f;
        for (int dy = 0; dy < 3; dy++) {
            int yy = 2 * py - 1 + dy; if ((unsigned)yy >= 10u) continue;
            for (int dx = 0; dx < 3; dx++) {
                int xx2 = 2 * pxx - 1 + dx; if ((unsigned)xx2 >= 10u) continue;
                mx = fmaxf(mx, ((float*)pin)[(o * 100 + yy * 10 + xx2) * 2 + img]);
            }
        }
        g_P2[((size_t)(b0 + img) * 128 + ocg * 32 + o) * 25 + p] = mx;
    }
}

// ---------- conv3/conv4 on 5x5, TWO images per block, packed f32x2, weight prefetch ----------
template <int CIN, bool TRANS>
__global__ void __launch_bounds__(128) conv5_kernel(int B) {
    __shared__ u64 pin[64 * 56];        // [ic][7][8] packed (img0,img1)
    __shared__ float sout[25 * 128];
    int b0 = blockIdx.y * 2, ocb = blockIdx.x * 128, tid = threadIdx.x;
    int oc = ocb + tid;
    const float* src = (CIN == 128) ? (g_P2 + 0) : (g_C3 + 0);
    int srcC = (CIN == 128) ? 128 : 256;
    const float* wt  = (CIN == 128) ? g_Wt3 : g_Wt4;
    const float* bf  = (CIN == 128) ? g_bf3 : g_bf4;
    u64 acc[25];
#pragma unroll
    for (int p = 0; p < 25; p++) acc[p] = 0ull;
    for (int i = tid; i < 64 * 56; i += 128) pin[i] = 0ull;
    for (int ch = 0; ch < CIN / 64; ch++) {
        __syncthreads();
        for (int i = tid; i < 3200; i += 128) {
            int ic = i / 50, r = i % 50, img = r / 25, p = r % 25;
            ((float*)pin)[((ic * 7 + p / 5 + 1) * 8 + p % 5 + 1) * 2 + img] =
                src[((size_t)(b0 + img) * srcC + ch * 64 + ic) * 25 + p];
        }
        __syncthreads();
        float wf[9];
#pragma unroll
        for (int j = 0; j < 9; j++) wf[j] = wt[(size_t)((ch * 64) * 9 + j) * 256 + oc];
        for (int icl = 0; icl < 64; icl++) {
            u64 w2[9];
#pragma unroll
            for (int j = 0; j < 9; j++) w2[j] = splat2(wf[j]);
            if (icl < 63) {
                int icn = ch * 64 + icl + 1;
#pragma unroll
                for (int j = 0; j < 9; j++) wf[j] = wt[(size_t)(icn * 9 + j) * 256 + oc];
            }
            const u64* base = &pin[icl * 56];
#pragma unroll
            for (int iy = 0; iy < 7; iy++) {
                u64 r2[8];
                const ulonglong2* rl = (const ulonglong2*)&base[iy * 8];
#pragma unroll
                for (int q = 0; q < 4; q++) { ulonglong2 t = rl[q]; r2[2*q] = t.x; r2[2*q+1] = t.y; }
#pragma unroll
                for (int y = 0; y < 5; y++) {
                    int ky = iy - y;
                    if (ky >= 0 && ky < 3) {
#pragma unroll
                        for (int kx = 0; kx < 3; kx++)
#pragma unroll
                        for (int xx = 0; xx < 5; xx++)
                            fma2(acc[y * 5 + xx], w2[ky * 3 + kx], r2[xx + kx]);
                    }
                }
            }
        }
    }
    float bias = bf[oc];
    if (TRANS) {
#pragma unroll
        for (int p = 0; p < 25; p++) {
            float2 f = unpack2(acc[p]);
            g_FT[((size_t)p * B + b0) * 256 + oc]     = fmaxf(f.x + bias, 0.f);
            g_FT[((size_t)p * B + b0 + 1) * 256 + oc] = fmaxf(f.y + bias, 0.f);
        }
    } else {
        for (int img = 0; img < 2; img++) {
            __syncthreads();
#pragma unroll
            for (int p = 0; p < 25; p++) {
                float2 f = unpack2(acc[p]);
                sout[p * 128 + tid] = fmaxf((img == 0 ? f.x : f.y) + bias, 0.f);
            }
            __syncthreads();
            float* dst = g_C3 + ((size_t)(b0 + img) * 256 + ocb) * 25;
            for (int i = tid; i < 3200; i += 128)
                dst[i] = sout[(i % 25) * 128 + (i / 25)];
        }
    }
}

// ---------- MLP layer 1: tile 128m x 128c, microtile 8m x 8c, pre-splatted B ----------
__global__ void __launch_bounds__(256) mlp1_kernel(const float* __restrict__ Wa,
                                                   const float* __restrict__ ba,
                                                   int stage2, int B) {
    __shared__ __align__(16) float As[16][128];
    __shared__ __align__(16) u64 Bs[16][128];
    int n = blockIdx.z, m0 = blockIdx.y * 128, c0 = blockIdx.x * 128;
    int tid = threadIdx.x, tm = tid >> 4, tn = tid & 15;
    int K = stage2 ? 336 : 256;
    int wofs = stage2 ? 0 : 80;
    const float* ft = g_FT + (size_t)n * B * 256;
    const float* nb = g_NB + (size_t)n * B * 80;
    const float* wa = Wa + (size_t)n * 336 * 600;
    u64 acc[4][8];
#pragma unroll
    for (int i = 0; i < 4; i++)
#pragma unroll
    for (int j = 0; j < 8; j++) acc[i][j] = 0ull;
    for (int kt = 0; kt < K; kt += 16) {
        // A tile: 512 float4 loads cover As[0..15][0..127]
        for (int i = tid; i < 512; i += 256) {
            int m = i >> 2, kq = (i & 3) * 4;     // 4 consecutive k
            const float* srcp;
            if (stage2 && kt < 80)
                srcp = &nb[(size_t)(m0 + m) * 80 + kt + kq];
            else
                srcp = &ft[(size_t)(m0 + m) * 256 + kt - (stage2 ? 80 : 0) + kq];
            float4 q = *(const float4*)srcp;
            As[kq + 0][m] = q.x; As[kq + 1][m] = q.y;
            As[kq + 2][m] = q.z; As[kq + 3][m] = q.w;
        }
        // B tile, pre-splatted to u64 (coalesced LDG)
        for (int i = tid; i < 2048; i += 256) {
            int kk = i >> 7, c = i & 127;
            int cg = c0 + c;
            float w = (cg < 600) ? wa[(size_t)(kt + kk + wofs) * 600 + cg] : 0.f;
            Bs[kk][c] = splat2(w);
        }
        __syncthreads();
#pragma unroll
        for (int kk = 0; kk < 16; kk++) {
            u64 a2[4];
            const ulonglong2* ap = (const ulonglong2*)&As[kk][tm * 8];
            ulonglong2 t0 = ap[0], t1 = ap[1];
            a2[0] = t0.x; a2[1] = t0.y; a2[2] = t1.x; a2[3] = t1.y;
            u64 b2[8];
            const ulonglong2* bp = (const ulonglong2*)&Bs[kk][tn * 8];
#pragma unroll
            for (int q = 0; q < 4; q++) { ulonglong2 t = bp[q]; b2[2*q] = t.x; b2[2*q+1] = t.y; }
#pragma unroll
            for (int i = 0; i < 4; i++)
#pragma unroll
            for (int j = 0; j < 8; j++) fma2(acc[i][j], a2[i], b2[j]);
        }
        __syncthreads();
    }
    const float* ban = ba + n * 600;
#pragma unroll
    for (int i = 0; i < 4; i++) {
        size_t r0 = ((size_t)n * B + m0 + tm * 8 + 2 * i) * 600;
        size_t r1 = r0 + 600;
#pragma unroll
        for (int j = 0; j < 8; j++) {
            int c = c0 + tn * 8 + j;
            if (c < 600) {
                float2 f = unpack2(acc[i][j]);
                float bb2 = ban[c];
                g_H[r0 + c] = tanhf(f.x + bb2);
                g_H[r1 + c] = tanhf(f.y + bb2);
            }
        }
    }
}

// ---------- MLP layer 2 (600->10) + softmax; 4 samples per warp ----------
__global__ void __launch_bounds__(256) mlp2_kernel(const float* __restrict__ Wb,
                                                   const float* __restrict__ bb,
                                                   int stage2, int B) {
    __shared__ float wbs[6000];
    __shared__ float bbs[10];
    int n = blockIdx.y, tid = threadIdx.x;
    for (int i = tid; i < 6000; i += 256) wbs[i] = Wb[(size_t)n * 6000 + i];
    if (tid < 10) bbs[tid] = bb[n * 10 + tid];
    __syncthreads();
    int warp = tid >> 5, lane = tid & 31;
    for (int s = 0; s < 4; s++) {
        int m = blockIdx.x * 32 + warp * 4 + s;
        const float* h = g_H + ((size_t)n * B + m) * 600;
        float lg[10];
#pragma unroll
        for (int c = 0; c < 10; c++) lg[c] = 0.f;
        for (int k = lane; k < 600; k += 32) {
            float hv = h[k];
#pragma unroll
            for (int c = 0; c < 10; c++) lg[c] += hv * wbs[k * 10 + c];
        }
#pragma unroll
        for (int off = 16; off; off >>= 1)
#pragma unroll
            for (int c = 0; c < 10; c++) lg[c] += __shfl_xor_sync(0xffffffffu, lg[c], off);
        if (lane == 0) {
            float mx = -1e30f;
#pragma unroll
            for (int c = 0; c < 10; c++) { lg[c] += bbs[c]; mx = fmaxf(mx, lg[c]); }
            float ssum = 0.f;
#pragma unroll
            for (int c = 0; c < 10; c++) { lg[c] = __expf(lg[c] - mx); ssum += lg[c]; }
            float inv = 1.f / ssum;
            float* o = (stage2 ? g_SEC : g_PRED) + ((size_t)n * B + m) * 10;
#pragma unroll
            for (int c = 0; c < 10; c++) o[c] = lg[c] * inv;
        }
    }
}

// ---------- neighbor gather ----------
__global__ void gather_kernel(int B) {
    size_t i = (size_t)blockIdx.x * blockDim.x + threadIdx.x;
    size_t total = (size_t)25 * B * 80;
    if (i >= total) return;
    int c = (int)(i % 10);
    int s = (int)((i / 10) % 8);
    size_t m = (i / 80) % B;
    int n = (int)(i / ((size_t)80 * B));
    int nb = g_NEI[n * 8 + s];
    g_NB[i] = (nb >= 0) ? g_PRED[((size_t)nb * B + m) * 10 + c] : 0.f;
}

// ---------- out[0:B*10) = mean; out[B*10:...) = second (if room) ----------
__global__ void finish_kernel(float* __restrict__ out, int B, int copy_second) {
    size_t nmean = (size_t)B * 10;
    size_t total = copy_second ? nmean + nmean * 25 : nmean;
    for (size_t i = (size_t)blockIdx.x * blockDim.x + threadIdx.x;
         i < total; i += (size_t)gridDim.x * blockDim.x) {
        if (i < nmean) {
            float s = 0.f;
#pragma unroll
            for (int n = 0; n < 25; n++) s += g_SEC[(size_t)n * nmean + i];
            out[i] = s * 0.04f;
        } else {
            out[i] = g_SEC[i - nmean];
        }
    }
}

extern "C" void kernel_launch(void* const* d_in, const int* in_sizes, int n_in,
                              void* d_out, int out_size) {
    const float* x = (const float*)d_in[0];
    int B = in_sizes[0] / 1200;
    // one setup launch: nei table + all BN folds (960,217 work items)
    setup_kernel<<<3751, 256>>>(
        (const float*)d_in[1],  (const float*)d_in[2],  (const float*)d_in[3],
        (const float*)d_in[4],  (const float*)d_in[5],  (const float*)d_in[6],
        (const float*)d_in[7],  (const float*)d_in[8],  (const float*)d_in[9],
        (const float*)d_in[10], (const float*)d_in[11], (const float*)d_in[12],
        (const float*)d_in[13], (const float*)d_in[14], (const float*)d_in[15],
        (const float*)d_in[16], (const float*)d_in[17], (const float*)d_in[18],
        (const float*)d_in[19], (const float*)d_in[20], (const float*)d_in[21],
        (const float*)d_in[22], (const float*)d_in[23], (const float*)d_in[24]);
    conv1_pool_kernel<<<B, 128>>>(x, B);
    conv2_pool_kernel<<<dim3(4, B / 2), 160>>>(B);
    conv5_kernel<128, false><<<dim3(2, B / 2), 128>>>(B);
    conv5_kernel<256, true><<<dim3(2, B / 2), 128>>>(B);
    const float* Wa = (const float*)d_in[25];
    const float* ba = (const float*)d_in[26];
    const float* Wb = (const float*)d_in[27];
    const float* bb = (const float*)d_in[28];
    float* out = (float*)d_out;
    // stage 1
    mlp1_kernel<<<dim3(5, B / 128, 25), 256>>>(Wa, ba, 0, B);
    mlp2_kernel<<<dim3(B / 32, 25), 256>>>(Wb, bb, 0, B);
    // gather neighbor predictions
    {
        size_t total = (size_t)25 * B * 80;
        gather_kernel<<<(unsigned)((total + 255) / 256), 256>>>(B);
    }
    // stage 2
    mlp1_kernel<<<dim3(5, B / 128, 25), 256>>>(Wa, ba, 1, B);
    mlp2_kernel<<<dim3(B / 32, 25), 256>>>(Wb, bb, 1, B);
    int copy_second = (out_size >= B * 10 + 25 * B * 10) ? 1 : 0;
    finish_kernel<<<2048, 256>>>(out, B, copy_second);
}

// round 12
// speedup vs baseline: 1.1996x; 1.1996x over previous
#include <cuda_runtime.h>
#include <math.h>
#include <stdint.h>

#define BMAX 8192
typedef unsigned long long u64;

// ---------- packed f32x2 helpers ----------
__device__ __forceinline__ u64 splat2(float w) {
    u64 r; asm("mov.b64 %0,{%1,%1};" : "=l"(r) : "f"(w)); return r;
}
__device__ __forceinline__ void fma2(u64& d, u64 a, u64 b) {
    asm("fma.rn.f32x2 %0,%1,%2,%0;" : "+l"(d) : "l"(a), "l"(b));
}
__device__ __forceinline__ float2 unpack2(u64 v) {
    float2 f; asm("mov.b64 {%0,%1},%2;" : "=f"(f.x), "=f"(f.y) : "l"(v)); return f;
}

// ---------- static scratch ----------
__device__ float g_P1[(size_t)BMAX * 64 * 100];   // pool1 [B][64][10][10]
__device__ float g_P2[(size_t)BMAX * 128 * 25];   // pool2 [B][128][5][5]
__device__ float g_C3[(size_t)BMAX * 256 * 25];   // conv3 [B][256][5][5]
__device__ float g_FT[(size_t)25 * BMAX * 256];   // feats [25][B][256]
__device__ float g_H [(size_t)25 * BMAX * 600];   // hidden [25][B][600]
__device__ float g_PRED[(size_t)25 * BMAX * 10];  // stage1 preds
__device__ float g_SEC [(size_t)25 * BMAX * 10];  // stage2 preds
__device__ float g_NB[(size_t)25 * BMAX * 80];    // neighbor concat
__device__ float g_Wt1[27 * 64],       g_bf1[64];
__device__ float g_Wt2[64 * 9 * 128],  g_bf2[128];
__device__ float g_Wt3[128 * 9 * 256], g_bf3[256];
__device__ float g_Wt4[256 * 9 * 256], g_bf4[256];
__device__ int   g_NEI[25 * 8];

// ---------- single setup kernel: neighbor table + all 4 BN-folds ----------
__global__ void setup_kernel(
    const float* __restrict__ W1, const float* __restrict__ b1, const float* __restrict__ gg1,
    const float* __restrict__ be1, const float* __restrict__ m1, const float* __restrict__ v1,
    const float* __restrict__ W2, const float* __restrict__ b2, const float* __restrict__ gg2,
    const float* __restrict__ be2, const float* __restrict__ m2, const float* __restrict__ v2,
    const float* __restrict__ W3, const float* __restrict__ b3, const float* __restrict__ gg3,
    const float* __restrict__ be3, const float* __restrict__ m3, const float* __restrict__ v3,
    const float* __restrict__ W4, const float* __restrict__ b4, const float* __restrict__ gg4,
    const float* __restrict__ be4, const float* __restrict__ m4, const float* __restrict__ v4) {
    size_t idx = (size_t)blockIdx.x * blockDim.x + threadIdx.x;
    if (idx < 25) {  // neighbor table (exact reference ordering)
        int i = (int)idx;
        const int w = 5, size = 25;
        int nb[8]; int c = 0;
        if (i - w >= 0)                           nb[c++] = i - w;
        if (i % w != 0)                           nb[c++] = i - 1;
        if ((i + 1) % w != 0)                     nb[c++] = i + 1;
        if (i + w < size)                         nb[c++] = i + w;
        if (i - w - 1 >= 0 && i % w != 0)         nb[c++] = i - w - 1;
        if (i - w + 1 >= 0 && (i + 1) % w != 0)   nb[c++] = i - w + 1;
        if (i + w - 1 < size && i % w != 0)       nb[c++] = i + w - 1;
        if (i + w + 1 < size && (i + 1) % w != 0) nb[c++] = i + w + 1;
        while (c < 8) nb[c++] = -1;
        for (int s = 0; s < 8; s++) g_NEI[i * 8 + s] = nb[s];
    }
    const float* Ws[4]  = {W1, W2, W3, W4};
    const float* bs[4]  = {b1, b2, b3, b4};
    const float* gs[4]  = {gg1, gg2, gg3, gg4};
    const float* bes[4] = {be1, be2, be3, be4};
    const float* ms[4]  = {m1, m2, m3, m4};
    const float* vs[4]  = {v1, v2, v3, v4};
    float* Wts[4] = {g_Wt1, g_Wt2, g_Wt3, g_Wt4};
    float* bfs[4] = {g_bf1, g_bf2, g_bf3, g_bf4};
    const int ci[4] = {3, 64, 128, 256}, co[4] = {64, 128, 256, 256};
    size_t off = 0;
    for (int l = 0; l < 4; l++) {
        size_t tot = (size_t)co[l] * ci[l] * 9;
        if (idx >= off && idx < off + tot) {
            int k = (int)(idx - off);
            int oc = k / (ci[l] * 9);
            int r  = k % (ci[l] * 9);
            float sc = gs[l][oc] / sqrtf(vs[l][oc] + 1e-5f);
            Wts[l][(size_t)r * co[l] + oc] = Ws[l][k] * sc;
            if (r == 0) bfs[l][oc] = (bs[l][oc] - ms[l][oc]) * sc + bes[l][oc];
        }
        off += tot;
    }
}

// ---------- conv1(3->64,20x20,p1)+BN+ReLU + pool3s2p1 (scalar; small) ----------
__global__ void __launch_bounds__(128) conv1_pool_kernel(const float* __restrict__ x, int B) {
    __shared__ float xin[3 * 22 * 22];
    __shared__ float ws[27 * 64];
    __shared__ float bsm[64];
    __shared__ float conv[8 * 400];
    int b = blockIdx.x, tid = threadIdx.x;
    for (int i = tid; i < 3 * 22 * 22; i += 128) xin[i] = 0.f;
    for (int i = tid; i < 27 * 64; i += 128) ws[i] = g_Wt1[i];
    if (tid < 64) bsm[tid] = g_bf1[tid];
    __syncthreads();
    const float* xb = x + (size_t)b * 1200;
    for (int i = tid; i < 1200; i += 128) {
        int c = i / 400, p = i % 400;
        xin[c * 484 + (p / 20 + 1) * 22 + (p % 20 + 1)] = xb[i];
    }
    __syncthreads();
    for (int ocb = 0; ocb < 64; ocb += 8) {
        for (int px = tid; px < 400; px += 128) {
            int y = px / 20, xx = px % 20;
            float in[27];
#pragma unroll
            for (int c = 0; c < 3; c++)
#pragma unroll
            for (int ky = 0; ky < 3; ky++)
#pragma unroll
            for (int kx = 0; kx < 3; kx++)
                in[c * 9 + ky * 3 + kx] = xin[c * 484 + (y + ky) * 22 + xx + kx];
#pragma unroll
            for (int o = 0; o < 8; o++) {
                float a = bsm[ocb + o];
#pragma unroll
                for (int j = 0; j < 27; j++) a += in[j] * ws[j * 64 + ocb + o];
                conv[o * 400 + px] = fmaxf(a, 0.f);
            }
        }
        __syncthreads();
        for (int i = tid; i < 800; i += 128) {
            int o = i / 100, p = i % 100, py = p / 10, pxx = p % 10;
            float mx = -1e30f;
            for (int dy = 0; dy < 3; dy++) {
                int yy = 2 * py - 1 + dy; if ((unsigned)yy >= 20u) continue;
                for (int dx = 0; dx < 3; dx++) {
                    int xx2 = 2 * pxx - 1 + dx; if ((unsigned)xx2 >= 20u) continue;
                    mx = fmaxf(mx, conv[o * 400 + yy * 20 + xx2]);
                }
            }
            g_P1[((size_t)b * 64 + ocb + o) * 100 + p] = mx;
        }
        __syncthreads();
    }
}

// ---------- conv2+pool, TWO images per block, packed f32x2, weight prefetch ----------
__global__ void __launch_bounds__(160) conv2_pool_kernel(int B) {
    __shared__ u64 pin[32 * 144];     // [ic][12][12] packed (img0,img1); reused for staging
    int b0 = blockIdx.y * 2, ocg = blockIdx.x, tid = threadIdx.x;
    int oc_l = tid & 31, rp = tid >> 5;
    int oc = ocg * 32 + oc_l;
    for (int i = tid; i < 32 * 144; i += 160) pin[i] = 0ull;
    u64 acc[2][10];
#pragma unroll
    for (int y = 0; y < 2; y++)
#pragma unroll
    for (int xx = 0; xx < 10; xx++) acc[y][xx] = 0ull;
    for (int ch = 0; ch < 2; ch++) {
        __syncthreads();
        for (int i = tid; i < 6400; i += 160) {
            int ic = i / 200, r = i % 200, img = r / 100, p = r % 100;
            ((float*)pin)[((ic * 12 + p / 10 + 1) * 12 + p % 10 + 1) * 2 + img] =
                g_P1[((size_t)(b0 + img) * 64 + ch * 32 + ic) * 100 + p];
        }
        __syncthreads();
        float wf[9];
#pragma unroll
        for (int j = 0; j < 9; j++) wf[j] = g_Wt2[((ch * 32) * 9 + j) * 128 + oc];
        for (int icl = 0; icl < 32; icl++) {
            u64 w2[9];
#pragma unroll
            for (int j = 0; j < 9; j++) w2[j] = splat2(wf[j]);
            if (icl < 31) {
                int icn = ch * 32 + icl + 1;
#pragma unroll
                for (int j = 0; j < 9; j++) wf[j] = g_Wt2[(icn * 9 + j) * 128 + oc];
            }
            const u64* base = &pin[icl * 144];
#pragma unroll
            for (int rr = 0; rr < 4; rr++) {
                int row = rp * 2 + rr;
                u64 r2[12];
                const ulonglong2* rl = (const ulonglong2*)&base[row * 12];
#pragma unroll
                for (int q = 0; q < 6; q++) { ulonglong2 t = rl[q]; r2[2*q] = t.x; r2[2*q+1] = t.y; }
#pragma unroll
                for (int y = 0; y < 2; y++) {
                    int ky = rr - y;
                    if (ky >= 0 && ky < 3) {
#pragma unroll
                        for (int kx = 0; kx < 3; kx++)
#pragma unroll
                        for (int xx = 0; xx < 10; xx++)
                            fma2(acc[y][xx], w2[ky * 3 + kx], r2[xx + kx]);
                    }
                }
            }
        }
    }
    float bias = g_bf2[oc];
    __syncthreads();
#pragma unroll
    for (int y = 0; y < 2; y++)
#pragma unroll
    for (int xx = 0; xx < 10; xx++) {
        float2 f = unpack2(acc[y][xx]);
        int px = (rp * 2 + y) * 10 + xx;
        ((float*)pin)[(oc_l * 100 + px) * 2 + 0] = fmaxf(f.x + bias, 0.f);
        ((float*)pin)[(oc_l * 100 + px) * 2 + 1] = fmaxf(f.y + bias, 0.f);
    }
    __syncthreads();
    for (int i = tid; i < 1600; i += 160) {
        int o = i / 50, r = i % 50, img = r / 25, p = r % 25;
        int py = p / 5, pxx = p % 5;
        float mx = -1e30f;
        for (int dy = 0; dy < 3; dy++) {
            int yy = 2 * py - 1 + dy; if ((unsigned)yy >= 10u) continue;
            for (int dx = 0; dx < 3; dx++) {
                int xx2 = 2 * pxx - 1 + dx; if ((unsigned)xx2 >= 10u) continue;
                mx = fmaxf(mx, ((float*)pin)[(o * 100 + yy * 10 + xx2) * 2 + img]);
            }
        }
        g_P2[((size_t)(b0 + img) * 128 + ocg * 32 + o) * 25 + p] = mx;
    }
}

// ---------- conv3/conv4 on 5x5, TWO images per block, packed f32x2, weight prefetch ----------
template <int CIN, bool TRANS>
__global__ void __launch_bounds__(128) conv5_kernel(int B) {
    __shared__ u64 pin[64 * 56];        // [ic][7][8] packed (img0,img1)
    __shared__ float sout[25 * 128];
    int b0 = blockIdx.y * 2, ocb = blockIdx.x * 128, tid = threadIdx.x;
    int oc = ocb + tid;
    const float* src = (CIN == 128) ? (g_P2 + 0) : (g_C3 + 0);
    int srcC = (CIN == 128) ? 128 : 256;
    const float* wt  = (CIN == 128) ? g_Wt3 : g_Wt4;
    const float* bf  = (CIN == 128) ? g_bf3 : g_bf4;
    u64 acc[25];
#pragma unroll
    for (int p = 0; p < 25; p++) acc[p] = 0ull;
    for (int i = tid; i < 64 * 56; i += 128) pin[i] = 0ull;
    for (int ch = 0; ch < CIN / 64; ch++) {
        __syncthreads();
        for (int i = tid; i < 3200; i += 128) {
            int ic = i / 50, r = i % 50, img = r / 25, p = r % 25;
            ((float*)pin)[((ic * 7 + p / 5 + 1) * 8 + p % 5 + 1) * 2 + img] =
                src[((size_t)(b0 + img) * srcC + ch * 64 + ic) * 25 + p];
        }
        __syncthreads();
        float wf[9];
#pragma unroll
        for (int j = 0; j < 9; j++) wf[j] = wt[(size_t)((ch * 64) * 9 + j) * 256 + oc];
        for (int icl = 0; icl < 64; icl++) {
            u64 w2[9];
#pragma unroll
            for (int j = 0; j < 9; j++) w2[j] = splat2(wf[j]);
            if (icl < 63) {
                int icn = ch * 64 + icl + 1;
#pragma unroll
                for (int j = 0; j < 9; j++) wf[j] = wt[(size_t)(icn * 9 + j) * 256 + oc];
            }
            const u64* base = &pin[icl * 56];
#pragma unroll
            for (int iy = 0; iy < 7; iy++) {
                u64 r2[8];
                const ulonglong2* rl = (const ulonglong2*)&base[iy * 8];
#pragma unroll
                for (int q = 0; q < 4; q++) { ulonglong2 t = rl[q]; r2[2*q] = t.x; r2[2*q+1] = t.y; }
#pragma unroll
                for (int y = 0; y < 5; y++) {
                    int ky = iy - y;
                    if (ky >= 0 && ky < 3) {
#pragma unroll
                        for (int kx = 0; kx < 3; kx++)
#pragma unroll
                        for (int xx = 0; xx < 5; xx++)
                            fma2(acc[y * 5 + xx], w2[ky * 3 + kx], r2[xx + kx]);
                    }
                }
            }
        }
    }
    float bias = bf[oc];
    if (TRANS) {
#pragma unroll
        for (int p = 0; p < 25; p++) {
            float2 f = unpack2(acc[p]);
            g_FT[((size_t)p * B + b0) * 256 + oc]     = fmaxf(f.x + bias, 0.f);
            g_FT[((size_t)p * B + b0 + 1) * 256 + oc] = fmaxf(f.y + bias, 0.f);
        }
    } else {
        for (int img = 0; img < 2; img++) {
            __syncthreads();
#pragma unroll
            for (int p = 0; p < 25; p++) {
                float2 f = unpack2(acc[p]);
                sout[p * 128 + tid] = fmaxf((img == 0 ? f.x : f.y) + bias, 0.f);
            }
            __syncthreads();
            float* dst = g_C3 + ((size_t)(b0 + img) * 256 + ocb) * 25;
            for (int i = tid; i < 3200; i += 128)
                dst[i] = sout[(i % 25) * 128 + (i / 25)];
        }
    }
}

// ---------- MLP layer 1: tile 128m x 64c, microtile 8m(4 pairs) x 4c, pre-splatted B ----------
__global__ void __launch_bounds__(256) mlp1_kernel(const float* __restrict__ Wa,
                                                   const float* __restrict__ ba,
                                                   int stage2, int B) {
    __shared__ __align__(16) float As[16][128];
    __shared__ __align__(16) u64 Bs[16][64];
    int n = blockIdx.z, m0 = blockIdx.y * 128, c0 = blockIdx.x * 64;
    int tid = threadIdx.x, tm = tid >> 4, tn = tid & 15;
    int K = stage2 ? 336 : 256;
    int wofs = stage2 ? 0 : 80;
    const float* ft = g_FT + (size_t)n * B * 256;
    const float* nb = g_NB + (size_t)n * B * 80;
    const float* wa = Wa + (size_t)n * 336 * 600;
    u64 acc[4][4];
#pragma unroll
    for (int i = 0; i < 4; i++)
#pragma unroll
    for (int j = 0; j < 4; j++) acc[i][j] = 0ull;
    for (int kt = 0; kt < K; kt += 16) {
        // A tile: 512 float4 loads cover As[0..15][0..127]
        for (int i = tid; i < 512; i += 256) {
            int m = i >> 2, kq = (i & 3) * 4;     // 4 consecutive k
            const float* srcp;
            if (stage2 && kt < 80)
                srcp = &nb[(size_t)(m0 + m) * 80 + kt + kq];
            else
                srcp = &ft[(size_t)(m0 + m) * 256 + kt - (stage2 ? 80 : 0) + kq];
            float4 q = *(const float4*)srcp;
            As[kq + 0][m] = q.x; As[kq + 1][m] = q.y;
            As[kq + 2][m] = q.z; As[kq + 3][m] = q.w;
        }
        // B tile, pre-splatted to u64 (coalesced LDG)
        for (int i = tid; i < 1024; i += 256) {
            int kk = i >> 6, c = i & 63;
            int cg = c0 + c;
            float w = (cg < 600) ? wa[(size_t)(kt + kk + wofs) * 600 + cg] : 0.f;
            Bs[kk][c] = splat2(w);
        }
        __syncthreads();
#pragma unroll
        for (int kk = 0; kk < 16; kk++) {
            u64 a2[4];
            const ulonglong2* ap = (const ulonglong2*)&As[kk][tm * 8];
            ulonglong2 t0 = ap[0], t1 = ap[1];
            a2[0] = t0.x; a2[1] = t0.y; a2[2] = t1.x; a2[3] = t1.y;
            u64 b2[4];
            const ulonglong2* bp = (const ulonglong2*)&Bs[kk][tn * 4];
            ulonglong2 u0 = bp[0], u1 = bp[1];
            b2[0] = u0.x; b2[1] = u0.y; b2[2] = u1.x; b2[3] = u1.y;
#pragma unroll
            for (int i = 0; i < 4; i++)
#pragma unroll
            for (int j = 0; j < 4; j++) fma2(acc[i][j], a2[i], b2[j]);
        }
        __syncthreads();
    }
    const float* ban = ba + n * 600;
#pragma unroll
    for (int i = 0; i < 4; i++) {
        size_t r0 = ((size_t)n * B + m0 + tm * 8 + 2 * i) * 600;
        size_t r1 = r0 + 600;
#pragma unroll
        for (int j = 0; j < 4; j++) {
            int c = c0 + tn * 4 + j;
            if (c < 600) {
                float2 f = unpack2(acc[i][j]);
                float bb2 = ban[c];
                g_H[r0 + c] = tanhf(f.x + bb2);
                g_H[r1 + c] = tanhf(f.y + bb2);
            }
        }
    }
}

// ---------- MLP layer 2 (600->10) + softmax; 4 samples per warp ----------
__global__ void __launch_bounds__(256) mlp2_kernel(const float* __restrict__ Wb,
                                                   const float* __restrict__ bb,
                                                   int stage2, int B) {
    __shared__ float wbs[6000];
    __shared__ float bbs[10];
    int n = blockIdx.y, tid = threadIdx.x;
    for (int i = tid; i < 6000; i += 256) wbs[i] = Wb[(size_t)n * 6000 + i];
    if (tid < 10) bbs[tid] = bb[n * 10 + tid];
    __syncthreads();
    int warp = tid >> 5, lane = tid & 31;
    for (int s = 0; s < 4; s++) {
        int m = blockIdx.x * 32 + warp * 4 + s;
        const float* h = g_H + ((size_t)n * B + m) * 600;
        float lg[10];
#pragma unroll
        for (int c = 0; c < 10; c++) lg[c] = 0.f;
        for (int k = lane; k < 600; k += 32) {
            float hv = h[k];
#pragma unroll
            for (int c = 0; c < 10; c++) lg[c] += hv * wbs[k * 10 + c];
        }
#pragma unroll
        for (int off = 16; off; off >>= 1)
#pragma unroll
            for (int c = 0; c < 10; c++) lg[c] += __shfl_xor_sync(0xffffffffu, lg[c], off);
        if (lane == 0) {
            float mx = -1e30f;
#pragma unroll
            for (int c = 0; c < 10; c++) { lg[c] += bbs[c]; mx = fmaxf(mx, lg[c]); }
            float ssum = 0.f;
#pragma unroll
            for (int c = 0; c < 10; c++) { lg[c] = __expf(lg[c] - mx); ssum += lg[c]; }
            float inv = 1.f / ssum;
            float* o = (stage2 ? g_SEC : g_PRED) + ((size_t)n * B + m) * 10;
#pragma unroll
            for (int c = 0; c < 10; c++) o[c] = lg[c] * inv;
        }
    }
}

// ---------- neighbor gather ----------
__global__ void gather_kernel(int B) {
    size_t i = (size_t)blockIdx.x * blockDim.x + threadIdx.x;
    size_t total = (size_t)25 * B * 80;
    if (i >= total) return;
    int c = (int)(i % 10);
    int s = (int)((i / 10) % 8);
    size_t m = (i / 80) % B;
    int n = (int)(i / ((size_t)80 * B));
    int nb = g_NEI[n * 8 + s];
    g_NB[i] = (nb >= 0) ? g_PRED[((size_t)nb * B + m) * 10 + c] : 0.f;
}

// ---------- out[0:B*10) = mean; out[B*10:...) = second (if room) ----------
__global__ void finish_kernel(float* __restrict__ out, int B, int copy_second) {
    size_t nmean = (size_t)B * 10;
    size_t total = copy_second ? nmean + nmean * 25 : nmean;
    for (size_t i = (size_t)blockIdx.x * blockDim.x + threadIdx.x;
         i < total; i += (size_t)gridDim.x * blockDim.x) {
        if (i < nmean) {
            float s = 0.f;
#pragma unroll
            for (int n = 0; n < 25; n++) s += g_SEC[(size_t)n * nmean + i];
            out[i] = s * 0.04f;
        } else {
            out[i] = g_SEC[i - nmean];
        }
    }
}

extern "C" void kernel_launch(void* const* d_in, const int* in_sizes, int n_in,
                              void* d_out, int out_size) {
    const float* x = (const float*)d_in[0];
    int B = in_sizes[0] / 1200;
    setup_kernel<<<3751, 256>>>(
        (const float*)d_in[1],  (const float*)d_in[2],  (const float*)d_in[3],
        (const float*)d_in[4],  (const float*)d_in[5],  (const float*)d_in[6],
        (const float*)d_in[7],  (const float*)d_in[8],  (const float*)d_in[9],
        (const float*)d_in[10], (const float*)d_in[11], (const float*)d_in[12],
        (const float*)d_in[13], (const float*)d_in[14], (const float*)d_in[15],
        (const float*)d_in[16], (const float*)d_in[17], (const float*)d_in[18],
        (const float*)d_in[19], (const float*)d_in[20], (const float*)d_in[21],
        (const float*)d_in[22], (const float*)d_in[23], (const float*)d_in[24]);
    conv1_pool_kernel<<<B, 128>>>(x, B);
    conv2_pool_kernel<<<dim3(4, B / 2), 160>>>(B);
    conv5_kernel<128, false><<<dim3(2, B / 2), 128>>>(B);
    conv5_kernel<256, true><<<dim3(2, B / 2), 128>>>(B);
    const float* Wa = (const float*)d_in[25];
    const float* ba = (const float*)d_in[26];
    const float* Wb = (const float*)d_in[27];
    const float* bb = (const float*)d_in[28];
    float* out = (float*)d_out;
    // stage 1
    mlp1_kernel<<<dim3(10, B / 128, 25), 256>>>(Wa, ba, 0, B);
    mlp2_kernel<<<dim3(B / 32, 25), 256>>>(Wb, bb, 0, B);
    // gather neighbor predictions
    {
        size_t total = (size_t)25 * B * 80;
        gather_kernel<<<(unsigned)((total + 255) / 256), 256>>>(B);
    }
    // stage 2
    mlp1_kernel<<<dim3(10, B / 128, 25), 256>>>(Wa, ba, 1, B);
    mlp2_kernel<<<dim3(B / 32, 25), 256>>>(Wb, bb, 1, B);
    int copy_second = (out_size >= B * 10 + 25 * B * 10) ? 1 : 0;
    finish_kernel<<<2048, 256>>>(out, B, copy_second);
}

// round 13
// speedup vs baseline: 1.4678x; 1.2236x over previous
#include <cuda_runtime.h>
#include <math.h>
#include <stdint.h>

#define BMAX 8192
typedef unsigned long long u64;

// ---------- packed f32x2 helpers ----------
__device__ __forceinline__ u64 splat2(float w) {
    u64 r; asm("mov.b64 %0,{%1,%1};" : "=l"(r) : "f"(w)); return r;
}
__device__ __forceinline__ void fma2(u64& d, u64 a, u64 b) {
    asm("fma.rn.f32x2 %0,%1,%2,%0;" : "+l"(d) : "l"(a), "l"(b));
}
__device__ __forceinline__ float2 unpack2(u64 v) {
    float2 f; asm("mov.b64 {%0,%1},%2;" : "=f"(f.x), "=f"(f.y) : "l"(v)); return f;
}

// ---------- static scratch ----------
__device__ float g_P1[(size_t)BMAX * 64 * 100];   // pool1 [B][64][10][10]
__device__ float g_P2[(size_t)BMAX * 128 * 25];   // pool2 [B][128][5][5]
__device__ float g_C3[(size_t)BMAX * 256 * 25];   // conv3 [B][256][5][5]
__device__ float g_FT[(size_t)25 * BMAX * 256];   // feats [25][B][256]
__device__ float g_H [(size_t)25 * BMAX * 600];   // hidden [25][B][600]
__device__ float g_PRED[(size_t)25 * BMAX * 10];  // stage1 preds
__device__ float g_SEC [(size_t)25 * BMAX * 10];  // stage2 preds
__device__ float g_NB[(size_t)25 * BMAX * 80];    // neighbor concat
__device__ float g_Wt1[27 * 64],       g_bf1[64];
__device__ float g_Wt2[64 * 9 * 128],  g_bf2[128];
__device__ float g_Wt3[128 * 9 * 256], g_bf3[256];
__device__ float g_Wt4[256 * 9 * 256], g_bf4[256];
__device__ int   g_NEI[25 * 8];

// ---------- single setup kernel: neighbor table + all 4 BN-folds ----------
__global__ void setup_kernel(
    const float* __restrict__ W1, const float* __restrict__ b1, const float* __restrict__ gg1,
    const float* __restrict__ be1, const float* __restrict__ m1, const float* __restrict__ v1,
    const float* __restrict__ W2, const float* __restrict__ b2, const float* __restrict__ gg2,
    const float* __restrict__ be2, const float* __restrict__ m2, const float* __restrict__ v2,
    const float* __restrict__ W3, const float* __restrict__ b3, const float* __restrict__ gg3,
    const float* __restrict__ be3, const float* __restrict__ m3, const float* __restrict__ v3,
    const float* __restrict__ W4, const float* __restrict__ b4, const float* __restrict__ gg4,
    const float* __restrict__ be4, const float* __restrict__ m4, const float* __restrict__ v4) {
    size_t idx = (size_t)blockIdx.x * blockDim.x + threadIdx.x;
    if (idx < 25) {  // neighbor table (exact reference ordering)
        int i = (int)idx;
        const int w = 5, size = 25;
        int nb[8]; int c = 0;
        if (i - w >= 0)                           nb[c++] = i - w;
        if (i % w != 0)                           nb[c++] = i - 1;
        if ((i + 1) % w != 0)                     nb[c++] = i + 1;
        if (i + w < size)                         nb[c++] = i + w;
        if (i - w - 1 >= 0 && i % w != 0)         nb[c++] = i - w - 1;
        if (i - w + 1 >= 0 && (i + 1) % w != 0)   nb[c++] = i - w + 1;
        if (i + w - 1 < size && i % w != 0)       nb[c++] = i + w - 1;
        if (i + w + 1 < size && (i + 1) % w != 0) nb[c++] = i + w + 1;
        while (c < 8) nb[c++] = -1;
        for (int s = 0; s < 8; s++) g_NEI[i * 8 + s] = nb[s];
    }
    const float* Ws[4]  = {W1, W2, W3, W4};
    const float* bs[4]  = {b1, b2, b3, b4};
    const float* gs[4]  = {gg1, gg2, gg3, gg4};
    const float* bes[4] = {be1, be2, be3, be4};
    const float* ms[4]  = {m1, m2, m3, m4};
    const float* vs[4]  = {v1, v2, v3, v4};
    float* Wts[4] = {g_Wt1, g_Wt2, g_Wt3, g_Wt4};
    float* bfs[4] = {g_bf1, g_bf2, g_bf3, g_bf4};
    const int ci[4] = {3, 64, 128, 256}, co[4] = {64, 128, 256, 256};
    size_t off = 0;
    for (int l = 0; l < 4; l++) {
        size_t tot = (size_t)co[l] * ci[l] * 9;
        if (idx >= off && idx < off + tot) {
            int k = (int)(idx - off);
            int oc = k / (ci[l] * 9);
            int r  = k % (ci[l] * 9);
            float sc = gs[l][oc] / sqrtf(vs[l][oc] + 1e-5f);
            Wts[l][(size_t)r * co[l] + oc] = Ws[l][k] * sc;
            if (r == 0) bfs[l][oc] = (bs[l][oc] - ms[l][oc]) * sc + bes[l][oc];
        }
        off += tot;
    }
}

// ---------- conv1(3->64,20x20,p1)+BN+ReLU + pool3s2p1 (scalar; small) ----------
__global__ void __launch_bounds__(128) conv1_pool_kernel(const float* __restrict__ x, int B) {
    __shared__ float xin[3 * 22 * 22];
    __shared__ float ws[27 * 64];
    __shared__ float bsm[64];
    __shared__ float conv[8 * 400];
    int b = blockIdx.x, tid = threadIdx.x;
    for (int i = tid; i < 3 * 22 * 22; i += 128) xin[i] = 0.f;
    for (int i = tid; i < 27 * 64; i += 128) ws[i] = g_Wt1[i];
    if (tid < 64) bsm[tid] = g_bf1[tid];
    __syncthreads();
    const float* xb = x + (size_t)b * 1200;
    for (int i = tid; i < 1200; i += 128) {
        int c = i / 400, p = i % 400;
        xin[c * 484 + (p / 20 + 1) * 22 + (p % 20 + 1)] = xb[i];
    }
    __syncthreads();
    for (int ocb = 0; ocb < 64; ocb += 8) {
        for (int px = tid; px < 400; px += 128) {
            int y = px / 20, xx = px % 20;
            float in[27];
#pragma unroll
            for (int c = 0; c < 3; c++)
#pragma unroll
            for (int ky = 0; ky < 3; ky++)
#pragma unroll
            for (int kx = 0; kx < 3; kx++)
                in[c * 9 + ky * 3 + kx] = xin[c * 484 + (y + ky) * 22 + xx + kx];
#pragma unroll
            for (int o = 0; o < 8; o++) {
                float a = bsm[ocb + o];
#pragma unroll
                for (int j = 0; j < 27; j++) a += in[j] * ws[j * 64 + ocb + o];
                conv[o * 400 + px] = fmaxf(a, 0.f);
            }
        }
        __syncthreads();
        for (int i = tid; i < 800; i += 128) {
            int o = i / 100, p = i % 100, py = p / 10, pxx = p % 10;
            float mx = -1e30f;
            for (int dy = 0; dy < 3; dy++) {
                int yy = 2 * py - 1 + dy; if ((unsigned)yy >= 20u) continue;
                for (int dx = 0; dx < 3; dx++) {
                    int xx2 = 2 * pxx - 1 + dx; if ((unsigned)xx2 >= 20u) continue;
                    mx = fmaxf(mx, conv[o * 400 + yy * 20 + xx2]);
                }
            }
            g_P1[((size_t)b * 64 + ocb + o) * 100 + p] = mx;
        }
        __syncthreads();
    }
}

// ---------- conv2+pool, TWO images per block, packed f32x2 (R10 form, no prefetch) ----------
__global__ void __launch_bounds__(160) conv2_pool_kernel(int B) {
    __shared__ u64 pin[32 * 144];     // [ic][12][12] packed (img0,img1); reused for staging
    int b0 = blockIdx.y * 2, ocg = blockIdx.x, tid = threadIdx.x;
    int oc_l = tid & 31, rp = tid >> 5;
    int oc = ocg * 32 + oc_l;
    for (int i = tid; i < 32 * 144; i += 160) pin[i] = 0ull;
    u64 acc[2][10];
#pragma unroll
    for (int y = 0; y < 2; y++)
#pragma unroll
    for (int xx = 0; xx < 10; xx++) acc[y][xx] = 0ull;
    for (int ch = 0; ch < 2; ch++) {
        __syncthreads();
        for (int i = tid; i < 6400; i += 160) {
            int ic = i / 200, r = i % 200, img = r / 100, p = r % 100;
            ((float*)pin)[((ic * 12 + p / 10 + 1) * 12 + p % 10 + 1) * 2 + img] =
                g_P1[((size_t)(b0 + img) * 64 + ch * 32 + ic) * 100 + p];
        }
        __syncthreads();
        for (int icl = 0; icl < 32; icl++) {
            int ic = ch * 32 + icl;
            u64 w2[9];
#pragma unroll
            for (int j = 0; j < 9; j++) w2[j] = splat2(g_Wt2[(ic * 9 + j) * 128 + oc]);
            const u64* base = &pin[icl * 144];
#pragma unroll
            for (int rr = 0; rr < 4; rr++) {
                int row = rp * 2 + rr;
                u64 r2[12];
                const ulonglong2* rl = (const ulonglong2*)&base[row * 12];
#pragma unroll
                for (int q = 0; q < 6; q++) { ulonglong2 t = rl[q]; r2[2*q] = t.x; r2[2*q+1] = t.y; }
#pragma unroll
                for (int y = 0; y < 2; y++) {
                    int ky = rr - y;
                    if (ky >= 0 && ky < 3) {
#pragma unroll
                        for (int kx = 0; kx < 3; kx++)
#pragma unroll
                        for (int xx = 0; xx < 10; xx++)
                            fma2(acc[y][xx], w2[ky * 3 + kx], r2[xx + kx]);
                    }
                }
            }
        }
    }
    float bias = g_bf2[oc];
    __syncthreads();
#pragma unroll
    for (int y = 0; y < 2; y++)
#pragma unroll
    for (int xx = 0; xx < 10; xx++) {
        float2 f = unpack2(acc[y][xx]);
        int px = (rp * 2 + y) * 10 + xx;
        ((float*)pin)[(oc_l * 100 + px) * 2 + 0] = fmaxf(f.x + bias, 0.f);
        ((float*)pin)[(oc_l * 100 + px) * 2 + 1] = fmaxf(f.y + bias, 0.f);
    }
    __syncthreads();
    for (int i = tid; i < 1600; i += 160) {
        int o = i / 50, r = i % 50, img = r / 25, p = r % 25;
        int py = p / 5, pxx = p % 5;
        float mx = -1e30f;
        for (int dy = 0; dy < 3; dy++) {
            int yy = 2 * py - 1 + dy; if ((unsigned)yy >= 10u) continue;
            for (int dx = 0; dx < 3; dx++) {
                int xx2 = 2 * pxx - 1 + dx; if ((unsigned)xx2 >= 10u) continue;
                mx = fmaxf(mx, ((float*)pin)[(o * 100 + yy * 10 + xx2) * 2 + img]);
            }
        }
        g_P2[((size_t)(b0 + img) * 128 + ocg * 32 + o) * 25 + p] = mx;
    }
}

// ---------- conv3/conv4 on 5x5, TWO images per block (R10 form, no prefetch) ----------
// __launch_bounds__(128, 5): cap regs ~102 so 5 blocks/SM are resident
template <int CIN, bool TRANS>
__global__ void __launch_bounds__(128, 5) conv5_kernel(int B) {
    __shared__ u64 pin[64 * 56];        // [ic][7][8] packed (img0,img1)
    __shared__ float sout[25 * 128];
    int b0 = blockIdx.y * 2, ocb = blockIdx.x * 128, tid = threadIdx.x;
    int oc = ocb + tid;
    const float* src = (CIN == 128) ? (g_P2 + 0) : (g_C3 + 0);
    int srcC = (CIN == 128) ? 128 : 256;
    const float* wt  = (CIN == 128) ? g_Wt3 : g_Wt4;
    const float* bf  = (CIN == 128) ? g_bf3 : g_bf4;
    u64 acc[25];
#pragma unroll
    for (int p = 0; p < 25; p++) acc[p] = 0ull;
    for (int i = tid; i < 64 * 56; i += 128) pin[i] = 0ull;
    for (int ch = 0; ch < CIN / 64; ch++) {
        __syncthreads();
        for (int i = tid; i < 3200; i += 128) {
            int ic = i / 50, r = i % 50, img = r / 25, p = r % 25;
            ((float*)pin)[((ic * 7 + p / 5 + 1) * 8 + p % 5 + 1) * 2 + img] =
                src[((size_t)(b0 + img) * srcC + ch * 64 + ic) * 25 + p];
        }
        __syncthreads();
        for (int icl = 0; icl < 64; icl++) {
            int ic = ch * 64 + icl;
            u64 w2[9];
#pragma unroll
            for (int j = 0; j < 9; j++) w2[j] = splat2(wt[(size_t)(ic * 9 + j) * 256 + oc]);
            const u64* base = &pin[icl * 56];
#pragma unroll
            for (int iy = 0; iy < 7; iy++) {
                u64 r2[8];
                const ulonglong2* rl = (const ulonglong2*)&base[iy * 8];
#pragma unroll
                for (int q = 0; q < 4; q++) { ulonglong2 t = rl[q]; r2[2*q] = t.x; r2[2*q+1] = t.y; }
#pragma unroll
                for (int y = 0; y < 5; y++) {
                    int ky = iy - y;
                    if (ky >= 0 && ky < 3) {
#pragma unroll
                        for (int kx = 0; kx < 3; kx++)
#pragma unroll
                        for (int xx = 0; xx < 5; xx++)
                            fma2(acc[y * 5 + xx], w2[ky * 3 + kx], r2[xx + kx]);
                    }
                }
            }
        }
    }
    float bias = bf[oc];
    if (TRANS) {
#pragma unroll
        for (int p = 0; p < 25; p++) {
            float2 f = unpack2(acc[p]);
            g_FT[((size_t)p * B + b0) * 256 + oc]     = fmaxf(f.x + bias, 0.f);
            g_FT[((size_t)p * B + b0 + 1) * 256 + oc] = fmaxf(f.y + bias, 0.f);
        }
    } else {
        for (int img = 0; img < 2; img++) {
            __syncthreads();
#pragma unroll
            for (int p = 0; p < 25; p++) {
                float2 f = unpack2(acc[p]);
                sout[p * 128 + tid] = fmaxf((img == 0 ? f.x : f.y) + bias, 0.f);
            }
            __syncthreads();
            float* dst = g_C3 + ((size_t)(b0 + img) * 256 + ocb) * 25;
            for (int i = tid; i < 3200; i += 128)
                dst[i] = sout[(i % 25) * 128 + (i / 25)];
        }
    }
}

// ---------- MLP layer 1 (R10 form): tile 128m x 64c, microtile 8m x 4c, float Bs ----------
__global__ void __launch_bounds__(256) mlp1_kernel(const float* __restrict__ Wa,
                                                   const float* __restrict__ ba,
                                                   int stage2, int B) {
    __shared__ __align__(16) float As[16][128];
    __shared__ __align__(16) float Bs[16][64];
    int n = blockIdx.z, m0 = blockIdx.y * 128, c0 = blockIdx.x * 64;
    int tid = threadIdx.x, tm = tid >> 4, tn = tid & 15;
    int K = stage2 ? 336 : 256;
    int wofs = stage2 ? 0 : 80;
    const float* ft = g_FT + (size_t)n * B * 256;
    const float* nb = g_NB + (size_t)n * B * 80;
    const float* wa = Wa + (size_t)n * 336 * 600;
    u64 acc[4][4];
#pragma unroll
    for (int i = 0; i < 4; i++)
#pragma unroll
    for (int j = 0; j < 4; j++) acc[i][j] = 0ull;
    for (int kt = 0; kt < K; kt += 16) {
        // A tile: 512 float4 loads cover As[0..15][0..127]
        for (int i = tid; i < 512; i += 256) {
            int m = i >> 2, kq = (i & 3) * 4;     // 4 consecutive k
            const float* srcp;
            if (stage2 && kt < 80)
                srcp = &nb[(size_t)(m0 + m) * 80 + kt + kq];
            else
                srcp = &ft[(size_t)(m0 + m) * 256 + kt - (stage2 ? 80 : 0) + kq];
            float4 q = *(const float4*)srcp;
            As[kq + 0][m] = q.x; As[kq + 1][m] = q.y;
            As[kq + 2][m] = q.z; As[kq + 3][m] = q.w;
        }
        // B tile (coalesced)
        for (int i = tid; i < 1024; i += 256) {
            int kk = i >> 6, c = i & 63;
            int cg = c0 + c;
            Bs[kk][c] = (cg < 600) ? wa[(size_t)(kt + kk + wofs) * 600 + cg] : 0.f;
        }
        __syncthreads();
#pragma unroll
        for (int kk = 0; kk < 16; kk++) {
            u64 a2[4];
            const ulonglong2* ap = (const ulonglong2*)&As[kk][tm * 8];
            ulonglong2 t0 = ap[0], t1 = ap[1];
            a2[0] = t0.x; a2[1] = t0.y; a2[2] = t1.x; a2[3] = t1.y;
            float4 bq = *(const float4*)&Bs[kk][tn * 4];
            u64 b2[4] = {splat2(bq.x), splat2(bq.y), splat2(bq.z), splat2(bq.w)};
#pragma unroll
            for (int i = 0; i < 4; i++)
#pragma unroll
            for (int j = 0; j < 4; j++) fma2(acc[i][j], a2[i], b2[j]);
        }
        __syncthreads();
    }
    const float* ban = ba + n * 600;
#pragma unroll
    for (int i = 0; i < 4; i++) {
        size_t r0 = ((size_t)n * B + m0 + tm * 8 + 2 * i) * 600;
        size_t r1 = r0 + 600;
#pragma unroll
        for (int j = 0; j < 4; j++) {
            int c = c0 + tn * 4 + j;
            if (c < 600) {
                float2 f = unpack2(acc[i][j]);
                float bb2 = ban[c];
                g_H[r0 + c] = tanhf(f.x + bb2);
                g_H[r1 + c] = tanhf(f.y + bb2);
            }
        }
    }
}

// ---------- MLP layer 2 (600->10) + softmax; 4 samples per warp ----------
__global__ void __launch_bounds__(256) mlp2_kernel(const float* __restrict__ Wb,
                                                   const float* __restrict__ bb,
                                                   int stage2, int B) {
    __shared__ float wbs[6000];
    __shared__ float bbs[10];
    int n = blockIdx.y, tid = threadIdx.x;
    for (int i = tid; i < 6000; i += 256) wbs[i] = Wb[(size_t)n * 6000 + i];
    if (tid < 10) bbs[tid] = bb[n * 10 + tid];
    __syncthreads();
    int warp = tid >> 5, lane = tid & 31;
    for (int s = 0; s < 4; s++) {
        int m = blockIdx.x * 32 + warp * 4 + s;
        const float* h = g_H + ((size_t)n * B + m) * 600;
        float lg[10];
#pragma unroll
        for (int c = 0; c < 10; c++) lg[c] = 0.f;
        for (int k = lane; k < 600; k += 32) {
            float hv = h[k];
#pragma unroll
            for (int c = 0; c < 10; c++) lg[c] += hv * wbs[k * 10 + c];
        }
#pragma unroll
        for (int off = 16; off; off >>= 1)
#pragma unroll
            for (int c = 0; c < 10; c++) lg[c] += __shfl_xor_sync(0xffffffffu, lg[c], off);
        if (lane == 0) {
            float mx = -1e30f;
#pragma unroll
            for (int c = 0; c < 10; c++) { lg[c] += bbs[c]; mx = fmaxf(mx, lg[c]); }
            float ssum = 0.f;
#pragma unroll
            for (int c = 0; c < 10; c++) { lg[c] = __expf(lg[c] - mx); ssum += lg[c]; }
            float inv = 1.f / ssum;
            float* o = (stage2 ? g_SEC : g_PRED) + ((size_t)n * B + m) * 10;
#pragma unroll
            for (int c = 0; c < 10; c++) o[c] = lg[c] * inv;
        }
    }
}

// ---------- neighbor gather ----------
__global__ void gather_kernel(int B) {
    size_t i = (size_t)blockIdx.x * blockDim.x + threadIdx.x;
    size_t total = (size_t)25 * B * 80;
    if (i >= total) return;
    int c = (int)(i % 10);
    int s = (int)((i / 10) % 8);
    size_t m = (i / 80) % B;
    int n = (int)(i / ((size_t)80 * B));
    int nb = g_NEI[n * 8 + s];
    g_NB[i] = (nb >= 0) ? g_PRED[((size_t)nb * B + m) * 10 + c] : 0.f;
}

// ---------- out[0:B*10) = mean; out[B*10:...) = second (if room) ----------
__global__ void finish_kernel(float* __restrict__ out, int B, int copy_second) {
    size_t nmean = (size_t)B * 10;
    size_t total = copy_second ? nmean + nmean * 25 : nmean;
    for (size_t i = (size_t)blockIdx.x * blockDim.x + threadIdx.x;
         i < total; i += (size_t)gridDim.x * blockDim.x) {
        if (i < nmean) {
            float s = 0.f;
#pragma unroll
            for (int n = 0; n < 25; n++) s += g_SEC[(size_t)n * nmean + i];
            out[i] = s * 0.04f;
        } else {
            out[i] = g_SEC[i - nmean];
        }
    }
}

extern "C" void kernel_launch(void* const* d_in, const int* in_sizes, int n_in,
                              void* d_out, int out_size) {
    const float* x = (const float*)d_in[0];
    int B = in_sizes[0] / 1200;
    setup_kernel<<<3751, 256>>>(
        (const float*)d_in[1],  (const float*)d_in[2],  (const float*)d_in[3],
        (const float*)d_in[4],  (const float*)d_in[5],  (const float*)d_in[6],
        (const float*)d_in[7],  (const float*)d_in[8],  (const float*)d_in[9],
        (const float*)d_in[10], (const float*)d_in[11], (const float*)d_in[12],
        (const float*)d_in[13], (const float*)d_in[14], (const float*)d_in[15],
        (const float*)d_in[16], (const float*)d_in[17], (const float*)d_in[18],
        (const float*)d_in[19], (const float*)d_in[20], (const float*)d_in[21],
        (const float*)d_in[22], (const float*)d_in[23], (const float*)d_in[24]);
    conv1_pool_kernel<<<B, 128>>>(x, B);
    conv2_pool_kernel<<<dim3(4, B / 2), 160>>>(B);
    conv5_kernel<128, false><<<dim3(2, B / 2), 128>>>(B);
    conv5_kernel<256, true><<<dim3(2, B / 2), 128>>>(B);
    const float* Wa = (const float*)d_in[25];
    const float* ba = (const float*)d_in[26];
    const float* Wb = (const float*)d_in[27];
    const float* bb = (const float*)d_in[28];
    float* out = (float*)d_out;
    // stage 1
    mlp1_kernel<<<dim3(10, B / 128, 25), 256>>>(Wa, ba, 0, B);
    mlp2_kernel<<<dim3(B / 32, 25), 256>>>(Wb, bb, 0, B);
    // gather neighbor predictions
    {
        size_t total = (size_t)25 * B * 80;
        gather_kernel<<<(unsigned)((total + 255) / 256), 256>>>(B);
    }
    // stage 2
    mlp1_kernel<<<dim3(10, B / 128, 25), 256>>>(Wa, ba, 1, B);
    mlp2_kernel<<<dim3(B / 32, 25), 256>>>(Wb, bb, 1, B);
    int copy_second = (out_size >= B * 10 + 25 * B * 10) ? 1 : 0;
    finish_kernel<<<2048, 256>>>(out, B, copy_second);
}

// round 15
// speedup vs baseline: 1.4827x; 1.0102x over previous
#include <cuda_runtime.h>
#include <math.h>
#include <stdint.h>

#define BMAX 8192
typedef unsigned long long u64;

// ---------- packed f32x2 helpers ----------
__device__ __forceinline__ u64 splat2(float w) {
    u64 r; asm("mov.b64 %0,{%1,%1};" : "=l"(r) : "f"(w)); return r;
}
__device__ __forceinline__ void fma2(u64& d, u64 a, u64 b) {
    asm("fma.rn.f32x2 %0,%1,%2,%0;" : "+l"(d) : "l"(a), "l"(b));
}
__device__ __forceinline__ float2 unpack2(u64 v) {
    float2 f; asm("mov.b64 {%0,%1},%2;" : "=f"(f.x), "=f"(f.y) : "l"(v)); return f;
}

// ---------- static scratch ----------
__device__ float g_P1[(size_t)BMAX * 64 * 100];   // pool1 [B][64][10][10]
__device__ float g_P2[(size_t)BMAX * 128 * 25];   // pool2 [B][128][5][5]
__device__ float g_C3[(size_t)BMAX * 256 * 25];   // conv3 [B][256][5][5]
__device__ float g_FT[(size_t)25 * BMAX * 256];   // feats [25][B][256]
__device__ float g_H [(size_t)25 * BMAX * 600];   // hidden [25][B][600]
__device__ float g_PRED[(size_t)25 * BMAX * 10];  // stage1 preds
__device__ float g_SEC [(size_t)25 * BMAX * 10];  // stage2 preds
__device__ float g_NB[(size_t)25 * BMAX * 80];    // neighbor concat
__device__ float g_Wt1[27 * 64],       g_bf1[64];
__device__ float g_Wt2[64 * 9 * 128],  g_bf2[128];
__device__ float g_Wt3[128 * 9 * 256], g_bf3[256];
__device__ float g_Wt4[256 * 9 * 256], g_bf4[256];
__device__ int   g_NEI[25 * 8];

// ---------- single setup kernel: neighbor table + all 4 BN-folds ----------
__global__ void setup_kernel(
    const float* __restrict__ W1, const float* __restrict__ b1, const float* __restrict__ gg1,
    const float* __restrict__ be1, const float* __restrict__ m1, const float* __restrict__ v1,
    const float* __restrict__ W2, const float* __restrict__ b2, const float* __restrict__ gg2,
    const float* __restrict__ be2, const float* __restrict__ m2, const float* __restrict__ v2,
    const float* __restrict__ W3, const float* __restrict__ b3, const float* __restrict__ gg3,
    const float* __restrict__ be3, const float* __restrict__ m3, const float* __restrict__ v3,
    const float* __restrict__ W4, const float* __restrict__ b4, const float* __restrict__ gg4,
    const float* __restrict__ be4, const float* __restrict__ m4, const float* __restrict__ v4) {
    size_t idx = (size_t)blockIdx.x * blockDim.x + threadIdx.x;
    if (idx < 25) {  // neighbor table (exact reference ordering)
        int i = (int)idx;
        const int w = 5, size = 25;
        int nb[8]; int c = 0;
        if (i - w >= 0)                           nb[c++] = i - w;
        if (i % w != 0)                           nb[c++] = i - 1;
        if ((i + 1) % w != 0)                     nb[c++] = i + 1;
        if (i + w < size)                         nb[c++] = i + w;
        if (i - w - 1 >= 0 && i % w != 0)         nb[c++] = i - w - 1;
        if (i - w + 1 >= 0 && (i + 1) % w != 0)   nb[c++] = i - w + 1;
        if (i + w - 1 < size && i % w != 0)       nb[c++] = i + w - 1;
        if (i + w + 1 < size && (i + 1) % w != 0) nb[c++] = i + w + 1;
        while (c < 8) nb[c++] = -1;
        for (int s = 0; s < 8; s++) g_NEI[i * 8 + s] = nb[s];
    }
    const float* Ws[4]  = {W1, W2, W3, W4};
    const float* bs[4]  = {b1, b2, b3, b4};
    const float* gs[4]  = {gg1, gg2, gg3, gg4};
    const float* bes[4] = {be1, be2, be3, be4};
    const float* ms[4]  = {m1, m2, m3, m4};
    const float* vs[4]  = {v1, v2, v3, v4};
    float* Wts[4] = {g_Wt1, g_Wt2, g_Wt3, g_Wt4};
    float* bfs[4] = {g_bf1, g_bf2, g_bf3, g_bf4};
    const int ci[4] = {3, 64, 128, 256}, co[4] = {64, 128, 256, 256};
    size_t off = 0;
    for (int l = 0; l < 4; l++) {
        size_t tot = (size_t)co[l] * ci[l] * 9;
        if (idx >= off && idx < off + tot) {
            int k = (int)(idx - off);
            int oc = k / (ci[l] * 9);
            int r  = k % (ci[l] * 9);
            float sc = gs[l][oc] / sqrtf(vs[l][oc] + 1e-5f);
            Wts[l][(size_t)r * co[l] + oc] = Ws[l][k] * sc;
            if (r == 0) bfs[l][oc] = (bs[l][oc] - ms[l][oc]) * sc + bes[l][oc];
        }
        off += tot;
    }
}

// ---------- conv1(3->64,20x20,p1)+BN+ReLU + pool3s2p1 (scalar; small) ----------
__global__ void __launch_bounds__(128) conv1_pool_kernel(const float* __restrict__ x, int B) {
    __shared__ float xin[3 * 22 * 22];
    __shared__ float ws[27 * 64];
    __shared__ float bsm[64];
    __shared__ float conv[8 * 400];
    int b = blockIdx.x, tid = threadIdx.x;
    for (int i = tid; i < 3 * 22 * 22; i += 128) xin[i] = 0.f;
    for (int i = tid; i < 27 * 64; i += 128) ws[i] = g_Wt1[i];
    if (tid < 64) bsm[tid] = g_bf1[tid];
    __syncthreads();
    const float* xb = x + (size_t)b * 1200;
    for (int i = tid; i < 1200; i += 128) {
        int c = i / 400, p = i % 400;
        xin[c * 484 + (p / 20 + 1) * 22 + (p % 20 + 1)] = xb[i];
    }
    __syncthreads();
    for (int ocb = 0; ocb < 64; ocb += 8) {
        for (int px = tid; px < 400; px += 128) {
            int y = px / 20, xx = px % 20;
            float in[27];
#pragma unroll
            for (int c = 0; c < 3; c++)
#pragma unroll
            for (int ky = 0; ky < 3; ky++)
#pragma unroll
            for (int kx = 0; kx < 3; kx++)
                in[c * 9 + ky * 3 + kx] = xin[c * 484 + (y + ky) * 22 + xx + kx];
#pragma unroll
            for (int o = 0; o < 8; o++) {
                float a = bsm[ocb + o];
#pragma unroll
                for (int j = 0; j < 27; j++) a += in[j] * ws[j * 64 + ocb + o];
                conv[o * 400 + px] = fmaxf(a, 0.f);
            }
        }
        __syncthreads();
        for (int i = tid; i < 800; i += 128) {
            int o = i / 100, p = i % 100, py = p / 10, pxx = p % 10;
            float mx = -1e30f;
            for (int dy = 0; dy < 3; dy++) {
                int yy = 2 * py - 1 + dy; if ((unsigned)yy >= 20u) continue;
                for (int dx = 0; dx < 3; dx++) {
                    int xx2 = 2 * pxx - 1 + dx; if ((unsigned)xx2 >= 20u) continue;
                    mx = fmaxf(mx, conv[o * 400 + yy * 20 + xx2]);
                }
            }
            g_P1[((size_t)b * 64 + ocb + o) * 100 + p] = mx;
        }
        __syncthreads();
    }
}

// ---------- conv2+pool, TWO images per block, f32x2, DOUBLE-BUFFERED staging ----------
// 4 chunks of 16 ics; buffer (ch&1); loads for ch+1 overlap compute of ch.
__global__ void __launch_bounds__(160) conv2_pool_kernel(int B) {
    __shared__ __align__(16) u64 pin[2][16 * 144];  // [ic][12][12] packed; 18.4KB each
    int b0 = blockIdx.y * 2, ocg = blockIdx.x, tid = threadIdx.x;
    int oc_l = tid & 31, rp = tid >> 5;
    int oc = ocg * 32 + oc_l;
    for (int i = tid; i < 2 * 16 * 144; i += 160) pin[0][i] = 0ull;  // zero pad both buffers
    u64 acc[2][10];
#pragma unroll
    for (int y = 0; y < 2; y++)
#pragma unroll
    for (int xx = 0; xx < 10; xx++) acc[y][xx] = 0ull;
    __syncthreads();
    // preload chunk 0 into buffer 0
    for (int i = tid; i < 3200; i += 160) {
        int ic = i / 200, r = i % 200, img = r / 100, p = r % 100;
        ((float*)pin[0])[((ic * 12 + p / 10 + 1) * 12 + p % 10 + 1) * 2 + img] =
            g_P1[((size_t)(b0 + img) * 64 + ic) * 100 + p];
    }
    __syncthreads();
    for (int ch = 0; ch < 4; ch++) {
        if (ch + 1 < 4) {  // issue next chunk's loads; overlap with compute below
            int buf = (ch + 1) & 1;
            for (int i = tid; i < 3200; i += 160) {
                int ic = i / 200, r = i % 200, img = r / 100, p = r % 100;
                ((float*)pin[buf])[((ic * 12 + p / 10 + 1) * 12 + p % 10 + 1) * 2 + img] =
                    g_P1[((size_t)(b0 + img) * 64 + (ch + 1) * 16 + ic) * 100 + p];
            }
        }
        const u64* pb = pin[ch & 1];
        for (int icl = 0; icl < 16; icl++) {
            int ic = ch * 16 + icl;
            u64 w2[9];
#pragma unroll
            for (int j = 0; j < 9; j++) w2[j] = splat2(g_Wt2[(ic * 9 + j) * 128 + oc]);
            const u64* base = &pb[icl * 144];
#pragma unroll
            for (int rr = 0; rr < 4; rr++) {
                int row = rp * 2 + rr;
                u64 r2[12];
                const ulonglong2* rl = (const ulonglong2*)&base[row * 12];
#pragma unroll
                for (int q = 0; q < 6; q++) { ulonglong2 t = rl[q]; r2[2*q] = t.x; r2[2*q+1] = t.y; }
#pragma unroll
                for (int y = 0; y < 2; y++) {
                    int ky = rr - y;
                    if (ky >= 0 && ky < 3) {
#pragma unroll
                        for (int kx = 0; kx < 3; kx++)
#pragma unroll
                        for (int xx = 0; xx < 10; xx++)
                            fma2(acc[y][xx], w2[ky * 3 + kx], r2[xx + kx]);
                    }
                }
            }
        }
        __syncthreads();  // next chunk's STS complete + this chunk's reads done
    }
    float bias = g_bf2[oc];
    // stage conv outputs (relu) into pin as floats: [oc_l][100]x2 (25.6KB, spans buffers)
#pragma unroll
    for (int y = 0; y < 2; y++)
#pragma unroll
    for (int xx = 0; xx < 10; xx++) {
        float2 f = unpack2(acc[y][xx]);
        int px = (rp * 2 + y) * 10 + xx;
        ((float*)pin)[(oc_l * 100 + px) * 2 + 0] = fmaxf(f.x + bias, 0.f);
        ((float*)pin)[(oc_l * 100 + px) * 2 + 1] = fmaxf(f.y + bias, 0.f);
    }
    __syncthreads();
    for (int i = tid; i < 1600; i += 160) {
        int o = i / 50, r = i % 50, img = r / 25, p = r % 25;
        int py = p / 5, pxx = p % 5;
        float mx = -1e30f;
        for (int dy = 0; dy < 3; dy++) {
            int yy = 2 * py - 1 + dy; if ((unsigned)yy >= 10u) continue;
            for (int dx = 0; dx < 3; dx++) {
                int xx2 = 2 * pxx - 1 + dx; if ((unsigned)xx2 >= 10u) continue;
                mx = fmaxf(mx, ((float*)pin)[(o * 100 + yy * 10 + xx2) * 2 + img]);
            }
        }
        g_P2[((size_t)(b0 + img) * 128 + ocg * 32 + o) * 25 + p] = mx;
    }
}

// ---------- conv3/conv4 on 5x5, TWO images per block, f32x2, DOUBLE-BUFFERED ----------
// chunks of 32 ics; __launch_bounds__(128, 5) keeps 5 blocks/SM (regs <= 102)
template <int CIN, bool TRANS>
__global__ void __launch_bounds__(128, 5) conv5_kernel(int B) {
    __shared__ __align__(16) u64 pin[2][32 * 56];   // [ic][7][8] packed; 14.3KB each
    __shared__ float sout[25 * 128];
    int b0 = blockIdx.y * 2, ocb = blockIdx.x * 128, tid = threadIdx.x;
    int oc = ocb + tid;
    const float* src = (CIN == 128) ? (g_P2 + 0) : (g_C3 + 0);
    int srcC = (CIN == 128) ? 128 : 256;
    const float* wt  = (CIN == 128) ? g_Wt3 : g_Wt4;
    const float* bf  = (CIN == 128) ? g_bf3 : g_bf4;
    u64 acc[25];
#pragma unroll
    for (int p = 0; p < 25; p++) acc[p] = 0ull;
    for (int i = tid; i < 2 * 32 * 56; i += 128) pin[0][i] = 0ull;  // zero pad both buffers
    __syncthreads();
    // preload chunk 0 into buffer 0
    for (int i = tid; i < 1600; i += 128) {
        int ic = i / 50, r = i % 50, img = r / 25, p = r % 25;
        ((float*)pin[0])[((ic * 7 + p / 5 + 1) * 8 + p % 5 + 1) * 2 + img] =
            src[((size_t)(b0 + img) * srcC + ic) * 25 + p];
    }
    __syncthreads();
    const int NCH = CIN / 32;
    for (int ch = 0; ch < NCH; ch++) {
        if (ch + 1 < NCH) {  // issue next chunk's loads; overlap with compute below
            int buf = (ch + 1) & 1;
            for (int i = tid; i < 1600; i += 128) {
                int ic = i / 50, r = i % 50, img = r / 25, p = r % 25;
                ((float*)pin[buf])[((ic * 7 + p / 5 + 1) * 8 + p % 5 + 1) * 2 + img] =
                    src[((size_t)(b0 + img) * srcC + (ch + 1) * 32 + ic) * 25 + p];
            }
        }
        const u64* pb = pin[ch & 1];
        for (int icl = 0; icl < 32; icl++) {
            int ic = ch * 32 + icl;
            u64 w2[9];
#pragma unroll
            for (int j = 0; j < 9; j++) w2[j] = splat2(wt[(size_t)(ic * 9 + j) * 256 + oc]);
            const u64* base = &pb[icl * 56];
#pragma unroll
            for (int iy = 0; iy < 7; iy++) {
                u64 r2[8];
                const ulonglong2* rl = (const ulonglong2*)&base[iy * 8];
#pragma unroll
                for (int q = 0; q < 4; q++) { ulonglong2 t = rl[q]; r2[2*q] = t.x; r2[2*q+1] = t.y; }
#pragma unroll
                for (int y = 0; y < 5; y++) {
                    int ky = iy - y;
                    if (ky >= 0 && ky < 3) {
#pragma unroll
                        for (int kx = 0; kx < 3; kx++)
#pragma unroll
                        for (int xx = 0; xx < 5; xx++)
                            fma2(acc[y * 5 + xx], w2[ky * 3 + kx], r2[xx + kx]);
                    }
                }
            }
        }
        __syncthreads();
    }
    float bias = bf[oc];
    if (TRANS) {
#pragma unroll
        for (int p = 0; p < 25; p++) {
            float2 f = unpack2(acc[p]);
            g_FT[((size_t)p * B + b0) * 256 + oc]     = fmaxf(f.x + bias, 0.f);
            g_FT[((size_t)p * B + b0 + 1) * 256 + oc] = fmaxf(f.y + bias, 0.f);
        }
    } else {
        for (int img = 0; img < 2; img++) {
            __syncthreads();
#pragma unroll
            for (int p = 0; p < 25; p++) {
                float2 f = unpack2(acc[p]);
                sout[p * 128 + tid] = fmaxf((img == 0 ? f.x : f.y) + bias, 0.f);
            }
            __syncthreads();
            float* dst = g_C3 + ((size_t)(b0 + img) * 256 + ocb) * 25;
            for (int i = tid; i < 3200; i += 128)
                dst[i] = sout[(i % 25) * 128 + (i / 25)];
        }
    }
}

// ---------- MLP layer 1 (R13 form): tile 128m x 64c, microtile 8m x 4c, float Bs ----------
__global__ void __launch_bounds__(256) mlp1_kernel(const float* __restrict__ Wa,
                                                   const float* __restrict__ ba,
                                                   int stage2, int B) {
    __shared__ __align__(16) float As[16][128];
    __shared__ __align__(16) float Bs[16][64];
    int n = blockIdx.z, m0 = blockIdx.y * 128, c0 = blockIdx.x * 64;
    int tid = threadIdx.x, tm = tid >> 4, tn = tid & 15;
    int K = stage2 ? 336 : 256;
    int wofs = stage2 ? 0 : 80;
    const float* ft = g_FT + (size_t)n * B * 256;
    const float* nb = g_NB + (size_t)n * B * 80;
    const float* wa = Wa + (size_t)n * 336 * 600;
    u64 acc[4][4];
#pragma unroll
    for (int i = 0; i < 4; i++)
#pragma unroll
    for (int j = 0; j < 4; j++) acc[i][j] = 0ull;
    for (int kt = 0; kt < K; kt += 16) {
        // A tile: 512 float4 loads cover As[0..15][0..127]
        for (int i = tid; i < 512; i += 256) {
            int m = i >> 2, kq = (i & 3) * 4;     // 4 consecutive k
            const float* srcp;
            if (stage2 && kt < 80)
                srcp = &nb[(size_t)(m0 + m) * 80 + kt + kq];
            else
                srcp = &ft[(size_t)(m0 + m) * 256 + kt - (stage2 ? 80 : 0) + kq];
            float4 q = *(const float4*)srcp;
            As[kq + 0][m] = q.x; As[kq + 1][m] = q.y;
            As[kq + 2][m] = q.z; As[kq + 3][m] = q.w;
        }
        // B tile (coalesced)
        for (int i = tid; i < 1024; i += 256) {
            int kk = i >> 6, c = i & 63;
            int cg = c0 + c;
            Bs[kk][c] = (cg < 600) ? wa[(size_t)(kt + kk + wofs) * 600 + cg] : 0.f;
        }
        __syncthreads();
#pragma unroll
        for (int kk = 0; kk < 16; kk++) {
            u64 a2[4];
            const ulonglong2* ap = (const ulonglong2*)&As[kk][tm * 8];
            ulonglong2 t0 = ap[0], t1 = ap[1];
            a2[0] = t0.x; a2[1] = t0.y; a2[2] = t1.x; a2[3] = t1.y;
            float4 bq = *(const float4*)&Bs[kk][tn * 4];
            u64 b2[4] = {splat2(bq.x), splat2(bq.y), splat2(bq.z), splat2(bq.w)};
#pragma unroll
            for (int i = 0; i < 4; i++)
#pragma unroll
            for (int j = 0; j < 4; j++) fma2(acc[i][j], a2[i], b2[j]);
        }
        __syncthreads();
    }
    const float* ban = ba + n * 600;
#pragma unroll
    for (int i = 0; i < 4; i++) {
        size_t r0 = ((size_t)n * B + m0 + tm * 8 + 2 * i) * 600;
        size_t r1 = r0 + 600;
#pragma unroll
        for (int j = 0; j < 4; j++) {
            int c = c0 + tn * 4 + j;
            if (c < 600) {
                float2 f = unpack2(acc[i][j]);
                float bb2 = ban[c];
                g_H[r0 + c] = tanhf(f.x + bb2);
                g_H[r1 + c] = tanhf(f.y + bb2);
            }
        }
    }
}

// ---------- MLP layer 2 (600->10) + softmax; 4 samples per warp ----------
__global__ void __launch_bounds__(256) mlp2_kernel(const float* __restrict__ Wb,
                                                   const float* __restrict__ bb,
                                                   int stage2, int B) {
    __shared__ float wbs[6000];
    __shared__ float bbs[10];
    int n = blockIdx.y, tid = threadIdx.x;
    for (int i = tid; i < 6000; i += 256) wbs[i] = Wb[(size_t)n * 6000 + i];
    if (tid < 10) bbs[tid] = bb[n * 10 + tid];
    __syncthreads();
    int warp = tid >> 5, lane = tid & 31;
    for (int s = 0; s < 4; s++) {
        int m = blockIdx.x * 32 + warp * 4 + s;
        const float* h = g_H + ((size_t)n * B + m) * 600;
        float lg[10];
#pragma unroll
        for (int c = 0; c < 10; c++) lg[c] = 0.f;
        for (int k = lane; k < 600; k += 32) {
            float hv = h[k];
#pragma unroll
            for (int c = 0; c < 10; c++) lg[c] += hv * wbs[k * 10 + c];
        }
#pragma unroll
        for (int off = 16; off; off >>= 1)
#pragma unroll
            for (int c = 0; c < 10; c++) lg[c] += __shfl_xor_sync(0xffffffffu, lg[c], off);
        if (lane == 0) {
            float mx = -1e30f;
#pragma unroll
            for (int c = 0; c < 10; c++) { lg[c] += bbs[c]; mx = fmaxf(mx, lg[c]); }
            float ssum = 0.f;
#pragma unroll
            for (int c = 0; c < 10; c++) { lg[c] = __expf(lg[c] - mx); ssum += lg[c]; }
            float inv = 1.f / ssum;
            float* o = (stage2 ? g_SEC : g_PRED) + ((size_t)n * B + m) * 10;
#pragma unroll
            for (int c = 0; c < 10; c++) o[c] = lg[c] * inv;
        }
    }
}

// ---------- neighbor gather ----------
__global__ void gather_kernel(int B) {
    size_t i = (size_t)blockIdx.x * blockDim.x + threadIdx.x;
    size_t total = (size_t)25 * B * 80;
    if (i >= total) return;
    int c = (int)(i % 10);
    int s = (int)((i / 10) % 8);
    size_t m = (i / 80) % B;
    int n = (int)(i / ((size_t)80 * B));
    int nb = g_NEI[n * 8 + s];
    g_NB[i] = (nb >= 0) ? g_PRED[((size_t)nb * B + m) * 10 + c] : 0.f;
}

// ---------- out[0:B*10) = mean; out[B*10:...) = second (if room) ----------
__global__ void finish_kernel(float* __restrict__ out, int B, int copy_second) {
    size_t nmean = (size_t)B * 10;
    size_t total = copy_second ? nmean + nmean * 25 : nmean;
    for (size_t i = (size_t)blockIdx.x * blockDim.x + threadIdx.x;
         i < total; i += (size_t)gridDim.x * blockDim.x) {
        if (i < nmean) {
            float s = 0.f;
#pragma unroll
            for (int n = 0; n < 25; n++) s += g_SEC[(size_t)n * nmean + i];
            out[i] = s * 0.04f;
        } else {
            out[i] = g_SEC[i - nmean];
        }
    }
}

extern "C" void kernel_launch(void* const* d_in, const int* in_sizes, int n_in,
                              void* d_out, int out_size) {
    const float* x = (const float*)d_in[0];
    int B = in_sizes[0] / 1200;
    setup_kernel<<<3751, 256>>>(
        (const float*)d_in[1],  (const float*)d_in[2],  (const float*)d_in[3],
        (const float*)d_in[4],  (const float*)d_in[5],  (const float*)d_in[6],
        (const float*)d_in[7],  (const float*)d_in[8],  (const float*)d_in[9],
        (const float*)d_in[10], (const float*)d_in[11], (const float*)d_in[12],
        (const float*)d_in[13], (const float*)d_in[14], (const float*)d_in[15],
        (const float*)d_in[16], (const float*)d_in[17], (const float*)d_in[18],
        (const float*)d_in[19], (const float*)d_in[20], (const float*)d_in[21],
        (const float*)d_in[22], (const float*)d_in[23], (const float*)d_in[24]);
    conv1_pool_kernel<<<B, 128>>>(x, B);
    conv2_pool_kernel<<<dim3(4, B / 2), 160>>>(B);
    conv5_kernel<128, false><<<dim3(2, B / 2), 128>>>(B);
    conv5_kernel<256, true><<<dim3(2, B / 2), 128>>>(B);
    const float* Wa = (const float*)d_in[25];
    const float* ba = (const float*)d_in[26];
    const float* Wb = (const float*)d_in[27];
    const float* bb = (const float*)d_in[28];
    float* out = (float*)d_out;
    // stage 1
    mlp1_kernel<<<dim3(10, B / 128, 25), 256>>>(Wa, ba, 0, B);
    mlp2_kernel<<<dim3(B / 32, 25), 256>>>(Wb, bb, 0, B);
    // gather neighbor predictions
    {
        size_t total = (size_t)25 * B * 80;
        gather_kernel<<<(unsigned)((total + 255) / 256), 256>>>(B);
    }
    // stage 2
    mlp1_kernel<<<dim3(10, B / 128, 25), 256>>>(Wa, ba, 1, B);
    mlp2_kernel<<<dim3(B / 32, 25), 256>>>(Wb, bb, 1, B);
    int copy_second = (out_size >= B * 10 + 25 * B * 10) ? 1 : 0;
    finish_kernel<<<2048, 256>>>(out, B, copy_second);
}